// round 16
// baseline (speedup 1.0000x reference)
#include <cuda_runtime.h>
#include <cuda_bf16.h>
#include <cuda_fp16.h>
#include <math.h>
#include <stdint.h>

// Problem constants
#define BB 16
#define TT 256
#define EE 256
#define HH 512
#define G4H 2048
#define VV 32000
#define MROWS 4096           // B*T, row r = t*16 + b
#define NC_LSTM 64           // lstm CTAs (8 hidden units each)
#define NC_ALL 148           // total resident CTAs (1/SM)
#define NTILE_N 125          // 32000 / 256
#define NTILES (32 * NTILE_N)
// main queue ranges
#define Q_SGEMM0 512
#define Q_TRANSB (Q_SGEMM0 + 16000)    // 16512
#define Q_DENSE  (Q_TRANSB + NTILES)   // 20512

// ------------------------- scratch (no mallocs allowed) -------------------------
__device__ float g_xw[(size_t)MROWS * G4H];       // xw1 = emb@W1+b1
__device__ __half g_h1rh[2][BB * HH];             // h1 ping-pong (fp16)
__device__ __half g_h2rh[2][BB * HH];             // h2 ping-pong (fp16)
__device__ __half g_ut[3 * (size_t)G4H * HH];     // U1^T|W2^T|U2^T fp16 [gc][k]
__device__ unsigned g_gcnt[16 * 64];              // 16 group counters, 256B apart
__device__ int g_prog;                            // lstm progress
__device__ unsigned g_wq;                         // main work queue
__device__ unsigned g_wq_tu;                      // transU queue (phase 0)
__device__ unsigned g_tudone;                     // transU completions
__device__ unsigned g_tbdone;                     // transB completions
__device__ unsigned g_xwrow[32];                  // per-m-row xw tile completions

__device__ __half g_a_h[(size_t)MROWS * HH];      // written by LSTM layer-2 gates
__device__ __half g_b_h[(size_t)VV * HH];         // [v][h] transposed Wd

// ------------------------- small PTX helpers ------------------------------------
__device__ __forceinline__ uint32_t smem_u32(const void* p) {
    uint32_t a;
    asm("{ .reg .u64 t; cvta.to.shared.u64 t, %1; cvt.u32.u64 %0, t; }" : "=r"(a) : "l"(p));
    return a;
}
__device__ __forceinline__ void cp_async16(uint32_t saddr, const void* gptr) {
    asm volatile("cp.async.cg.shared.global [%0], [%1], 16;"
                 :: "r"(saddr), "l"(__cvta_generic_to_global(gptr)) : "memory");
}
__device__ __forceinline__ void cp_commit() {
    asm volatile("cp.async.commit_group;" ::: "memory");
}
template<int N>
__device__ __forceinline__ void cp_wait() {
    asm volatile("cp.async.wait_group %0;" :: "n"(N) : "memory");
}
__device__ __forceinline__ void ldm_x4(uint32_t* r, uint32_t a) {
    asm volatile("ldmatrix.sync.aligned.m8n8.x4.shared.b16 {%0,%1,%2,%3}, [%4];"
                 : "=r"(r[0]), "=r"(r[1]), "=r"(r[2]), "=r"(r[3]) : "r"(a));
}
__device__ __forceinline__ void mma_f16(float* d, const uint32_t* a, uint32_t b0, uint32_t b1) {
    asm volatile(
        "mma.sync.aligned.m16n8k16.row.col.f32.f16.f16.f32 "
        "{%0,%1,%2,%3}, {%4,%5,%6,%7}, {%8,%9}, {%0,%1,%2,%3};"
        : "+f"(d[0]), "+f"(d[1]), "+f"(d[2]), "+f"(d[3])
        : "r"(a[0]), "r"(a[1]), "r"(a[2]), "r"(a[3]), "r"(b0), "r"(b1));
}
__device__ __forceinline__ float fsigmoid(float x) {
    return __fdividef(1.f, 1.f + __expf(-x));
}
__device__ __forceinline__ float ftanh(float x) {
    return 1.f - __fdividef(2.f, __expf(2.f * x) + 1.f);
}

// ------------------------- grouped-counter barrier (64 lstm CTAs) ---------------
__device__ __forceinline__ void grid_barrier_grp(unsigned target4, int lane, int wid, int ct) {
    __syncthreads();
    if (wid == 0) {
        __threadfence();
        if (lane == 0)
            atomicAdd(&g_gcnt[(ct & 15) * 64], 1u);
        volatile unsigned* cp = &g_gcnt[(lane & 15) * 64];
        bool ok;
        do {
            unsigned v = *cp;
            ok = __all_sync(0xffffffffu, v >= target4);
        } while (!ok);
        __threadfence();
    }
    __syncthreads();
}

// ------------------------- init kernel (state reset, graph-replay safe) ---------
__global__ void init_kernel()
{
    int t = threadIdx.x;
    if (t < 16) g_gcnt[t * 64] = 0;
    if (t < 32) g_xwrow[t] = 0;
    if (t == 32) g_prog = -1;
    if (t == 33) g_wq = 0;
    if (t == 34) g_wq_tu = 0;
    if (t == 35) g_tudone = 0;
    if (t == 36) g_tbdone = 0;
}

// ------------------------- queued jobs (512 threads each) -----------------------
// transU: U[512][2048] fp32 -> g_ut[mat][2048][512] fp16, 32x32 tile
__device__ void job_transU(char* lsm, int tb,
                           const float* __restrict__ U1,
                           const float* __restrict__ W2,
                           const float* __restrict__ U2, int tid)
{
    __half (*sh)[33] = (__half(*)[33])lsm;
    int mat = tb >> 10;
    int t2 = tb & 1023;
    int k0 = (t2 & 15) * 32;
    int g0 = (t2 >> 4) * 32;
    const float* src = (mat == 0) ? U1 : (mat == 1) ? W2 : U2;
    int tx = tid & 31, ty = tid >> 5;   // ty 0..15
#pragma unroll
    for (int j = 0; j < 2; j++) {
        int kr = ty + j * 16;
        sh[kr][tx] = __float2half(src[(size_t)(k0 + kr) * G4H + g0 + tx]);
    }
    __syncthreads();
#pragma unroll
    for (int j = 0; j < 2; j++) {
        int gr = ty + j * 16;
        g_ut[(size_t)mat * G4H * HH + (size_t)(g0 + gr) * HH + k0 + tx] = sh[tx][gr];
    }
    __threadfence();
    __syncthreads();
    if (tid == 0) atomicAdd(&g_tudone, 1u);
    __syncthreads();
}

// transB: Wd[512][32000] fp32 -> g_b_h[32000][512] fp16, 32x32 tile (v-major)
__device__ void job_transB(char* lsm, int tb, const float* __restrict__ Wd, int tid)
{
    __half (*sh)[33] = (__half(*)[33])lsm;
    int v0 = (tb >> 4) * 32;
    int h0 = (tb & 15) * 32;
    int tx = tid & 31, ty = tid >> 5;
#pragma unroll
    for (int j = 0; j < 2; j++) {
        int hr = ty + j * 16;
        sh[hr][tx] = __float2half(Wd[(size_t)(h0 + hr) * VV + v0 + tx]);
    }
    __syncthreads();
#pragma unroll
    for (int j = 0; j < 2; j++) {
        int vr = ty + j * 16;
        g_b_h[(size_t)(v0 + vr) * HH + h0 + tx] = sh[tx][vr];
    }
    __threadfence();
    __syncthreads();
    if (tid == 0) atomicAdd(&g_tbdone, 1u);
    __syncthreads();
}

// sgemm0: xw1 tile 128x128 (K=256), 512 threads, 4x8 micro-tiles
__device__ void job_sgemm0(char* lsm, int mi, int nj,
                           const float* __restrict__ emb,
                           const float* __restrict__ W1,
                           const float* __restrict__ b1,
                           const int* __restrict__ tokens, int tid)
{
    float (*As)[128] = (float(*)[128])lsm;
    float (*Bs)[128] = (float(*)[128])(lsm + 8192);
    const int m0 = mi * 128, n0 = nj * 128;
    const int rg = (tid >> 4) * 4;     // 0..124
    const int cg = (tid & 15) * 4;     // 0..60

    float acc[4][8];
#pragma unroll
    for (int i = 0; i < 4; i++)
#pragma unroll
        for (int j = 0; j < 8; j++) acc[i][j] = 0.f;

    for (int kt = 0; kt < EE; kt += 16) {
        __syncthreads();
        {
            int m = tid >> 2, kq = tid & 3;
            int gr = m0 + m;
            int tok = tokens[((gr & 15) << 8) + (gr >> 4)];
            float4 v = *(const float4*)(emb + (size_t)tok * EE + kt + kq * 4);
            As[kq * 4 + 0][m] = v.x;
            As[kq * 4 + 1][m] = v.y;
            As[kq * 4 + 2][m] = v.z;
            As[kq * 4 + 3][m] = v.w;
        }
        {
            int k = tid >> 5, n4 = tid & 31;
            float4 v = *(const float4*)(W1 + (size_t)(kt + k) * G4H + n0 + n4 * 4);
            *(float4*)&Bs[k][n4 * 4] = v;
        }
        __syncthreads();
#pragma unroll
        for (int kk = 0; kk < 16; kk++) {
            float4 a4 = *(const float4*)&As[kk][rg];
            float4 b0 = *(const float4*)&Bs[kk][cg];
            float4 b1v = *(const float4*)&Bs[kk][64 + cg];
            float a[4] = {a4.x, a4.y, a4.z, a4.w};
            float b[8] = {b0.x, b0.y, b0.z, b0.w, b1v.x, b1v.y, b1v.z, b1v.w};
#pragma unroll
            for (int i = 0; i < 4; i++)
#pragma unroll
                for (int j = 0; j < 8; j++)
                    acc[i][j] += a[i] * b[j];
        }
    }

    float bj[8];
#pragma unroll
    for (int j = 0; j < 4; j++) {
        bj[j]     = b1[n0 + cg + j];
        bj[4 + j] = b1[n0 + 64 + cg + j];
    }
#pragma unroll
    for (int i = 0; i < 4; i++) {
        int r = m0 + rg + i;
        float4 o0, o1;
        o0.x = acc[i][0] + bj[0]; o0.y = acc[i][1] + bj[1];
        o0.z = acc[i][2] + bj[2]; o0.w = acc[i][3] + bj[3];
        o1.x = acc[i][4] + bj[4]; o1.y = acc[i][5] + bj[5];
        o1.z = acc[i][6] + bj[6]; o1.w = acc[i][7] + bj[7];
        *(float4*)&g_xw[(size_t)r * G4H + n0 + cg]      = o0;
        *(float4*)&g_xw[(size_t)r * G4H + n0 + 64 + cg] = o1;
    }
    __threadfence();
    __syncthreads();
    if (tid == 0) atomicAdd(&g_xwrow[mi], 1u);
    __syncthreads();
}

// ------------------------- dense worker tile (512 threads, 128x256) -------------
#define DWSTG 30720u

__device__ __forceinline__ void dw_load(uint32_t sb, int m0, int n0, int c, int tid)
{
    const uint32_t stg = sb + (uint32_t)(c % 3) * DWSTG;
    const int kc0 = c * 32;
#pragma unroll
    for (int it = 0; it < 3; it++) {
        int u = tid + it * 512;
        int isB = (u >= 512);
        int u2 = isB ? (u - 512) : u;
        int r = u2 >> 2, q = u2 & 3;
        const __half* g = isB ? g_b_h : g_a_h;
        int grow = isB ? n0 : m0;
        uint32_t base = isB ? 10240u : 0u;
        cp_async16(stg + base + (uint32_t)(r * 80 + q * 16),
                   g + (size_t)(grow + r) * HH + kc0 + q * 8);
    }
    cp_commit();
}

__device__ void dw_tile(uint32_t sb, int m0, int n0,
                        const float* __restrict__ bd, float* __restrict__ out,
                        int tid, int wid, int lane)
{
    const int wm = wid & 1;
    const int wn = wid >> 1;
    const int lrow = lane & 15;
    const int lsel = (lane >> 4) << 4;

    float acc[4][4][4];
#pragma unroll
    for (int mt = 0; mt < 4; mt++)
#pragma unroll
        for (int nt = 0; nt < 4; nt++)
#pragma unroll
            for (int e = 0; e < 4; e++) acc[mt][nt][e] = 0.f;

    dw_load(sb, m0, n0, 0, tid);
    dw_load(sb, m0, n0, 1, tid);

    for (int c = 0; c < 16; c++) {
        if (c < 15) cp_wait<1>(); else cp_wait<0>();
        __syncthreads();
        if (c + 2 < 16) dw_load(sb, m0, n0, c + 2, tid);

        const uint32_t stg = sb + (uint32_t)(c % 3) * DWSTG;
        const uint32_t a_b = stg + (uint32_t)((wm * 64 + lrow) * 80) + lsel;
        const uint32_t b_b = stg + 10240u + (uint32_t)((wn * 32 + lrow) * 80) + lsel;
#pragma unroll
        for (int s = 0; s < 2; s++) {
            uint32_t bf[2][4];
#pragma unroll
            for (int i = 0; i < 2; i++)
                ldm_x4(bf[i], b_b + (uint32_t)(i * 16 * 80 + s * 32));
#pragma unroll
            for (int mt = 0; mt < 4; mt++) {
                uint32_t a[4];
                ldm_x4(a, a_b + (uint32_t)(mt * 16 * 80 + s * 32));
#pragma unroll
                for (int nt = 0; nt < 4; nt++) {
                    uint32_t b0 = bf[nt >> 1][nt & 1];
                    uint32_t b1 = bf[nt >> 1][(nt & 1) + 2];
                    mma_f16(acc[mt][nt], a, b0, b1);
                }
            }
        }
    }

    const int g = lane >> 2;
    const int tig = lane & 3;
#pragma unroll
    for (int nt = 0; nt < 4; nt++) {
        int col = n0 + wn * 32 + nt * 8 + tig * 2;
        float b0 = __ldg(bd + col);
        float b1 = __ldg(bd + col + 1);
#pragma unroll
        for (int mt = 0; mt < 4; mt++) {
            int r0 = m0 + wm * 64 + mt * 16 + g;
            int r1 = r0 + 8;
            size_t o0 = (size_t)((r0 & 15) * 256 + (r0 >> 4));
            size_t o1 = (size_t)((r1 & 15) * 256 + (r1 >> 4));
            float2 v0 = make_float2(acc[mt][nt][0] + b0, acc[mt][nt][1] + b1);
            float2 v1 = make_float2(acc[mt][nt][2] + b0, acc[mt][nt][3] + b1);
            *(float2*)(out + o0 * VV + col) = v0;
            *(float2*)(out + o1 * VV + col) = v1;
        }
    }
    __syncthreads();
}

// ------------------------- worker loop (main queue) -----------------------------
__device__ void worker_loop(char* lsm,
                            const float* __restrict__ emb,
                            const float* __restrict__ W1,
                            const float* __restrict__ b1,
                            const int* __restrict__ tokens,
                            const float* __restrict__ Wd,
                            const float* __restrict__ bd,
                            float* __restrict__ out,
                            int tid, int wid, int lane)
{
    __shared__ int s_idx;
    for (;;) {
        if (tid == 0) s_idx = (int)atomicAdd(&g_wq, 1u);
        __syncthreads();
        int idx = s_idx;
        if (idx < Q_SGEMM0) {
            job_sgemm0(lsm, idx >> 4, idx & 15, emb, W1, b1, tokens, tid);
        } else if (idx < Q_TRANSB) {
            job_transB(lsm, idx - Q_SGEMM0, Wd, tid);
        } else if (idx < Q_DENSE) {
            int d = idx - Q_TRANSB;
            int mi = d / NTILE_N, nj = d - mi * NTILE_N;
            if (tid == 0) {
                while (*(volatile unsigned*)&g_tbdone < 16000u) { }
                while (*(volatile int*)&g_prog < 8 * mi + 8) { }
                __threadfence();
            }
            __syncthreads();
            dw_tile(smem_u32(lsm), mi * 128, nj * 256, bd, out, tid, wid, lane);
        } else {
            break;
        }
    }
}

// ------------------------- fused persistent kernel ------------------------------
#define LSTM_SMEM 157696
__global__ __launch_bounds__(512, 1)
void fused_kernel(const float* __restrict__ emb,
                  const float* __restrict__ W1,
                  const float* __restrict__ b1,
                  const int* __restrict__ tokens,
                  const float* __restrict__ Wd,
                  const float* __restrict__ U1,
                  const float* __restrict__ W2,
                  const float* __restrict__ U2,
                  const float* __restrict__ b2,
                  const float* __restrict__ bd,
                  float* __restrict__ out)
{
    extern __shared__ char lsm[];
    __shared__ int tu_idx;

    const int tid = threadIdx.x;
    const int wid = tid >> 5;
    const int lane = tid & 31;
    const int bid = blockIdx.x;

    // ---- phase 0: all CTAs cooperate on transU ----
    for (;;) {
        if (tid == 0) tu_idx = (int)atomicAdd(&g_wq_tu, 1u);
        __syncthreads();
        int idx = tu_idx;
        if (idx >= 3072) break;
        job_transU(lsm, idx, U1, W2, U2, tid);
    }

    if (bid >= NC_LSTM) {
        worker_loop(lsm, emb, W1, b1, tokens, Wd, bd, out, tid, wid, lane);
        return;
    }

    // ---- lstm role: wait for transU completion ----
    if (tid == 0) {
        while (*(volatile unsigned*)&g_tudone < 3072u) { }
        __threadfence();
    }
    __syncthreads();

    char* Bsl = lsm;
    char* h1st = lsm + 99840;
    char* h2st = lsm + 116480;
    float* zp = (float*)(lsm + 133120);

    const int ct = bid;
    const int hu0 = ct * 8;
    const uint32_t Bsl_a = smem_u32(Bsl);
    const uint32_t h1_a = smem_u32(h1st);
    const uint32_t h2_a = smem_u32(h2st);

    for (int i = tid; i < 6144; i += 512) {
        int mat = i >> 11;
        int rem = i & 2047;
        int n = rem >> 6;
        int ch = rem & 63;
        int gc = (n >> 3) * HH + hu0 + (n & 7);
        cp_async16(Bsl_a + (uint32_t)(mat * 33280 + n * 1040 + ch * 16),
                   g_ut + (size_t)mat * G4H * HH + (size_t)gc * HH + ch * 8);
    }
    cp_commit();
    for (int i = tid; i < 2080; i += 512)
        *(uint4*)(h1st + i * 16) = make_uint4(0, 0, 0, 0);
    cp_wait<0>();
    __syncthreads();

    const int rb = wid;
    const int rn = lane;
    const int rgc = (rn >> 3) * HH + hu0 + (rn & 7);
    const float b2v = __ldg(b2 + rgc);
    const int u7 = rn & 7;

    float creg = 0.f;

    const uint32_t lrow = (uint32_t)(lane & 15) * 1040u;
    const uint32_t lsel = (uint32_t)((lane >> 4) << 4);

    for (int s = 0; s <= TT; s++) {
        // gate on xw row readiness (new row every 8 steps)
        if (s < TT && (s & 7) == 0) {
            if (tid == 0) {
                while (*(volatile unsigned*)&g_xwrow[s >> 3] < 16u) { }
                __threadfence();
            }
            __syncthreads();
        }
        float xwv = (s < TT) ? __ldg(&g_xw[((size_t)s * BB + rb) * G4H + rgc]) : 0.f;

        if (s >= 1) {
            const __half* hp = g_h1rh[(s - 1) & 1];
#pragma unroll
            for (int i = 0; i < 2; i++) {
                int u = tid + i * 512;
                int b = u >> 6, ch = u & 63;
                cp_async16(h1_a + (uint32_t)(b * 1040 + ch * 16), hp + b * HH + ch * 8);
            }
            if (s >= 2) {
                const __half* hq = g_h2rh[s & 1];
#pragma unroll
                for (int i = 0; i < 2; i++) {
                    int u = tid + i * 512;
                    int b = u >> 6, ch = u & 63;
                    cp_async16(h2_a + (uint32_t)(b * 1040 + ch * 16), hq + b * HH + ch * 8);
                }
            }
            cp_commit();
            cp_wait<0>();
        }
        __syncthreads();

#pragma unroll
        for (int jj = 0; jj < 2; jj++) {
            int j = (jj == 0) ? wid : (16 + wid);
            if (j < 24) {
                int mat = j >> 3;
                int rem = j & 7;
                int ntile = rem >> 2;
                int ksl = rem & 3;
                uint32_t Ab = ((mat == 2) ? h2_a : h1_a) + (uint32_t)(ksl * 256) + lrow + lsel;
                uint32_t Bb = Bsl_a + (uint32_t)(mat * 33280 + ntile * 16 * 1040 + ksl * 256)
                              + lrow + lsel;
                float acc[2][4] = {{0.f, 0.f, 0.f, 0.f}, {0.f, 0.f, 0.f, 0.f}};
#pragma unroll
                for (int c = 0; c < 8; c++) {
                    uint32_t a[4], bf[4];
                    ldm_x4(a, Ab + (uint32_t)(c * 32));
                    ldm_x4(bf, Bb + (uint32_t)(c * 32));
                    mma_f16(acc[0], a, bf[0], bf[2]);
                    mma_f16(acc[1], a, bf[1], bf[3]);
                }
                int r0 = lane >> 2, c0 = (lane & 3) * 2;
                float* zj = zp + j * 256;
#pragma unroll
                for (int nt = 0; nt < 2; nt++) {
                    zj[r0 * 16 + nt * 8 + c0]           = acc[nt][0];
                    zj[r0 * 16 + nt * 8 + c0 + 1]       = acc[nt][1];
                    zj[(r0 + 8) * 16 + nt * 8 + c0]     = acc[nt][2];
                    zj[(r0 + 8) * 16 + nt * 8 + c0 + 1] = acc[nt][3];
                }
            }
        }
        __syncthreads();

        {
            int ntile = rn >> 4;
            int o16 = rb * 16 + (rn & 15);
            float z1 = xwv, z2 = b2v;
#pragma unroll
            for (int ksl = 0; ksl < 4; ksl++) {
                z1 += zp[(ntile * 4 + ksl) * 256 + o16];
                z2 += zp[(8 + ntile * 4 + ksl) * 256 + o16]
                    + zp[(16 + ntile * 4 + ksl) * 256 + o16];
            }
            float a0 = __shfl_sync(0xffffffffu, z1, u7);
            float a1 = __shfl_sync(0xffffffffu, z1, 8 + u7);
            float a2 = __shfl_sync(0xffffffffu, z1, 16 + u7);
            float a3 = __shfl_sync(0xffffffffu, z1, 24 + u7);
            float d0 = __shfl_sync(0xffffffffu, z2, u7);
            float d1 = __shfl_sync(0xffffffffu, z2, 8 + u7);
            float d2 = __shfl_sync(0xffffffffu, z2, 16 + u7);
            float d3 = __shfl_sync(0xffffffffu, z2, 24 + u7);

            if (rn < 8) {
                if (s < TT) {
                    float ig = fsigmoid(a0);
                    float fg = fsigmoid(a1);
                    float gg = ftanh(a2);
                    float og = fsigmoid(a3);
                    creg = fg * creg + ig * gg;
                    g_h1rh[s & 1][rb * HH + hu0 + u7] = __float2half(og * ftanh(creg));
                }
            } else if (rn < 16) {
                if (s >= 1) {
                    int t = s - 1;
                    float ig = fsigmoid(d0);
                    float fg = fsigmoid(d1);
                    float gg = ftanh(d2);
                    float og = fsigmoid(d3);
                    creg = fg * creg + ig * gg;
                    float h = og * ftanh(creg);
                    __half hh = __float2half(h);
                    g_h2rh[t & 1][rb * HH + hu0 + u7] = hh;
                    g_a_h[((size_t)t * BB + rb) * HH + hu0 + u7] = hh;
                }
            }
        }

        grid_barrier_grp((unsigned)(4 * (s + 1)), lane, wid, ct);
        if (ct == 0 && tid == 0)
            *(volatile int*)&g_prog = s;
    }

    // ---- lstm CTAs join the dense tail ----
    worker_loop(lsm, emb, W1, b1, tokens, Wd, bd, out, tid, wid, lane);
}

// ------------------------- launch -----------------------------------------------
extern "C" void kernel_launch(void* const* d_in, const int* in_sizes, int n_in,
                              void* d_out, int out_size)
{
    const int*   tokens = (const int*)  d_in[0];
    const float* emb    = (const float*)d_in[1];
    const float* W1     = (const float*)d_in[2];
    const float* U1     = (const float*)d_in[3];
    const float* b1     = (const float*)d_in[4];
    const float* W2     = (const float*)d_in[5];
    const float* U2     = (const float*)d_in[6];
    const float* b2     = (const float*)d_in[7];
    const float* Wd     = (const float*)d_in[8];
    const float* bd     = (const float*)d_in[9];
    float* out = (float*)d_out;

    cudaFuncSetAttribute(fused_kernel, cudaFuncAttributeMaxDynamicSharedMemorySize,
                         LSTM_SMEM);

    // 1) tiny state reset (graph-replay safe)
    init_kernel<<<1, 64>>>();
    // 2) single persistent kernel: transU (all CTAs) -> LSTM producer (64 CTAs)
    //    + prep/dense workers (84 CTAs), lstm CTAs join dense tail
    fused_kernel<<<NC_ALL, 512, LSTM_SMEM>>>(emb, W1, b1, tokens, Wd, U1, W2, U2,
                                             b2, bd, out);
}

// round 17
// speedup vs baseline: 1.1051x; 1.1051x over previous
#include <cuda_runtime.h>
#include <cuda_bf16.h>
#include <cuda_fp16.h>
#include <math.h>
#include <stdint.h>

// Problem constants
#define BB 16
#define TT 256
#define EE 256
#define HH 512
#define G4H 2048
#define VV 32000
#define MROWS 4096           // B*T, row r = t*16 + b
#define NC_LSTM 64           // lstm CTAs (8 hidden units each)
#define NC_ALL 148           // total resident CTAs (1/SM)
#define NTILE_N 125          // 32000 / 256
#define NTILES (32 * NTILE_N)
// worker queue ranges: sgemm0 (m-major) -> transB (big tiles) -> dense (gated)
#define QN_SGEMM0 512
#define QN_TRANSB 4000
#define Q_TB_END (QN_SGEMM0 + QN_TRANSB)     // 4512
#define Q_DN_END (Q_TB_END + NTILES)         // 8512

// ------------------------- scratch (no mallocs allowed) -------------------------
__device__ float g_xw[(size_t)MROWS * G4H];       // xw1 = emb@W1+b1
__device__ __half g_h1rh[2][BB * HH];             // h1 ping-pong (fp16)
__device__ __half g_h2rh[2][BB * HH];             // h2 ping-pong (fp16)
__device__ __half g_ut[3 * (size_t)G4H * HH];     // U1^T|W2^T|U2^T fp16 [gc][k]
__device__ unsigned g_gcnt[16 * 64];              // 16 group counters, 256B apart
__device__ int g_prog;                            // lstm progress
__device__ unsigned g_wq;                         // worker queue
__device__ unsigned g_tbdone;                     // transB completions
__device__ unsigned g_xwrow[32];                  // per-m-row xw tile completions

__device__ __half g_a_h[(size_t)MROWS * HH];      // written by LSTM layer-2 gates
__device__ __half g_b_h[(size_t)VV * HH];         // [v][h] transposed Wd

// ------------------------- small PTX helpers ------------------------------------
__device__ __forceinline__ uint32_t smem_u32(const void* p) {
    uint32_t a;
    asm("{ .reg .u64 t; cvta.to.shared.u64 t, %1; cvt.u32.u64 %0, t; }" : "=r"(a) : "l"(p));
    return a;
}
__device__ __forceinline__ void cp_async16(uint32_t saddr, const void* gptr) {
    asm volatile("cp.async.cg.shared.global [%0], [%1], 16;"
                 :: "r"(saddr), "l"(__cvta_generic_to_global(gptr)) : "memory");
}
__device__ __forceinline__ void cp_commit() {
    asm volatile("cp.async.commit_group;" ::: "memory");
}
template<int N>
__device__ __forceinline__ void cp_wait() {
    asm volatile("cp.async.wait_group %0;" :: "n"(N) : "memory");
}
__device__ __forceinline__ void ldm_x4(uint32_t* r, uint32_t a) {
    asm volatile("ldmatrix.sync.aligned.m8n8.x4.shared.b16 {%0,%1,%2,%3}, [%4];"
                 : "=r"(r[0]), "=r"(r[1]), "=r"(r[2]), "=r"(r[3]) : "r"(a));
}
__device__ __forceinline__ void mma_f16(float* d, const uint32_t* a, uint32_t b0, uint32_t b1) {
    asm volatile(
        "mma.sync.aligned.m16n8k16.row.col.f32.f16.f16.f32 "
        "{%0,%1,%2,%3}, {%4,%5,%6,%7}, {%8,%9}, {%0,%1,%2,%3};"
        : "+f"(d[0]), "+f"(d[1]), "+f"(d[2]), "+f"(d[3])
        : "r"(a[0]), "r"(a[1]), "r"(a[2]), "r"(a[3]), "r"(b0), "r"(b1));
}
__device__ __forceinline__ float fsigmoid(float x) {
    return __fdividef(1.f, 1.f + __expf(-x));
}
__device__ __forceinline__ float ftanh(float x) {
    return 1.f - __fdividef(2.f, __expf(2.f * x) + 1.f);
}

// ------------------------- grouped-counter barrier (64 lstm CTAs) ---------------
__device__ __forceinline__ void grid_barrier_grp(unsigned target4, int lane, int wid, int ct) {
    __syncthreads();
    if (wid == 0) {
        __threadfence();
        if (lane == 0)
            atomicAdd(&g_gcnt[(ct & 15) * 64], 1u);
        volatile unsigned* cp = &g_gcnt[(lane & 15) * 64];
        bool ok;
        do {
            unsigned v = *cp;
            ok = __all_sync(0xffffffffu, v >= target4);
        } while (!ok);
        __threadfence();
    }
    __syncthreads();
}

// ------------------------- init kernel (state reset, graph-replay safe) ---------
__global__ void init_kernel()
{
    int t = threadIdx.x;
    if (t < 16) g_gcnt[t * 64] = 0;
    if (t < 32) g_xwrow[t] = 0;
    if (t == 32) g_prog = -1;
    if (t == 33) g_wq = 0;
    if (t == 34) g_tbdone = 0;
}

// ------------------------- prep: transU only (3072 blocks x 256 thr) ------------
__global__ __launch_bounds__(256, 2)
void prep_kernel(const float* __restrict__ U1,
                 const float* __restrict__ W2,
                 const float* __restrict__ U2)
{
    __shared__ __half sh2[32][33];
    const int tb = blockIdx.x;
    const int tid = threadIdx.x;
    int mat = tb >> 10;
    int t2 = tb & 1023;
    int k0 = (t2 & 15) * 32;
    int g0 = (t2 >> 4) * 32;
    const float* src = (mat == 0) ? U1 : (mat == 1) ? W2 : U2;
    int tx = tid & 31, ty = tid >> 5;
#pragma unroll
    for (int j = 0; j < 4; j++) {
        int kr = ty + j * 8;
        sh2[kr][tx] = __float2half(src[(size_t)(k0 + kr) * G4H + g0 + tx]);
    }
    __syncthreads();
#pragma unroll
    for (int j = 0; j < 4; j++) {
        int gr = ty + j * 8;
        g_ut[(size_t)mat * G4H * HH + (size_t)(g0 + gr) * HH + k0 + tx] = sh2[tx][gr];
    }
}

// ------------------------- queued jobs (512 threads each) -----------------------
// sgemm0: xw1 tile 128x128 (K=256), 4x8 micro-tiles (proven in R16)
__device__ void job_sgemm0(char* lsm, int mi, int nj,
                           const float* __restrict__ emb,
                           const float* __restrict__ W1,
                           const float* __restrict__ b1,
                           const int* __restrict__ tokens, int tid)
{
    float (*As)[128] = (float(*)[128])lsm;
    float (*Bs)[128] = (float(*)[128])(lsm + 8192);
    const int m0 = mi * 128, n0 = nj * 128;
    const int rg = (tid >> 4) * 4;
    const int cg = (tid & 15) * 4;

    float acc[4][8];
#pragma unroll
    for (int i = 0; i < 4; i++)
#pragma unroll
        for (int j = 0; j < 8; j++) acc[i][j] = 0.f;

    for (int kt = 0; kt < EE; kt += 16) {
        __syncthreads();
        {
            int m = tid >> 2, kq = tid & 3;
            int gr = m0 + m;
            int tok = tokens[((gr & 15) << 8) + (gr >> 4)];
            float4 v = *(const float4*)(emb + (size_t)tok * EE + kt + kq * 4);
            As[kq * 4 + 0][m] = v.x;
            As[kq * 4 + 1][m] = v.y;
            As[kq * 4 + 2][m] = v.z;
            As[kq * 4 + 3][m] = v.w;
        }
        {
            int k = tid >> 5, n4 = tid & 31;
            float4 v = *(const float4*)(W1 + (size_t)(kt + k) * G4H + n0 + n4 * 4);
            *(float4*)&Bs[k][n4 * 4] = v;
        }
        __syncthreads();
#pragma unroll
        for (int kk = 0; kk < 16; kk++) {
            float4 a4 = *(const float4*)&As[kk][rg];
            float4 b0 = *(const float4*)&Bs[kk][cg];
            float4 b1v = *(const float4*)&Bs[kk][64 + cg];
            float a[4] = {a4.x, a4.y, a4.z, a4.w};
            float b[8] = {b0.x, b0.y, b0.z, b0.w, b1v.x, b1v.y, b1v.z, b1v.w};
#pragma unroll
            for (int i = 0; i < 4; i++)
#pragma unroll
                for (int j = 0; j < 8; j++)
                    acc[i][j] += a[i] * b[j];
        }
    }

    float bj[8];
#pragma unroll
    for (int j = 0; j < 4; j++) {
        bj[j]     = b1[n0 + cg + j];
        bj[4 + j] = b1[n0 + 64 + cg + j];
    }
#pragma unroll
    for (int i = 0; i < 4; i++) {
        int r = m0 + rg + i;
        float4 o0, o1;
        o0.x = acc[i][0] + bj[0]; o0.y = acc[i][1] + bj[1];
        o0.z = acc[i][2] + bj[2]; o0.w = acc[i][3] + bj[3];
        o1.x = acc[i][4] + bj[4]; o1.y = acc[i][5] + bj[5];
        o1.z = acc[i][6] + bj[6]; o1.w = acc[i][7] + bj[7];
        *(float4*)&g_xw[(size_t)r * G4H + n0 + cg]      = o0;
        *(float4*)&g_xw[(size_t)r * G4H + n0 + 64 + cg] = o1;
    }
    __threadfence();
    __syncthreads();
    if (tid == 0) atomicAdd(&g_xwrow[mi], 1u);
    __syncthreads();
}

// transB big tile: Wd[512][32000] fp32 -> g_b_h[32000][512] fp16, 64h x 64v
__device__ void job_transB(char* lsm, int tb, const float* __restrict__ Wd, int tid)
{
    __half (*sh)[66] = (__half(*)[66])lsm;
    int v0 = (tb % 500) * 64;
    int h0 = (tb / 500) * 64;
#pragma unroll
    for (int i = 0; i < 8; i++) {
        int idx = tid + i * 512;
        int hr = idx >> 6, vc = idx & 63;
        sh[hr][vc] = __float2half(Wd[(size_t)(h0 + hr) * VV + v0 + vc]);
    }
    __syncthreads();
#pragma unroll
    for (int i = 0; i < 8; i++) {
        int idx = tid + i * 512;
        int vr = idx >> 6, hc = idx & 63;
        g_b_h[(size_t)(v0 + vr) * HH + h0 + hc] = sh[hc][vr];
    }
    __threadfence();
    __syncthreads();
    if (tid == 0) atomicAdd(&g_tbdone, 1u);
    __syncthreads();
}

// ------------------------- dense worker tile (512 threads, 128x256) -------------
#define DWSTG 30720u

__device__ __forceinline__ void dw_load(uint32_t sb, int m0, int n0, int c, int tid)
{
    const uint32_t stg = sb + (uint32_t)(c % 3) * DWSTG;
    const int kc0 = c * 32;
#pragma unroll
    for (int it = 0; it < 3; it++) {
        int u = tid + it * 512;
        int isB = (u >= 512);
        int u2 = isB ? (u - 512) : u;
        int r = u2 >> 2, q = u2 & 3;
        const __half* g = isB ? g_b_h : g_a_h;
        int grow = isB ? n0 : m0;
        uint32_t base = isB ? 10240u : 0u;
        cp_async16(stg + base + (uint32_t)(r * 80 + q * 16),
                   g + (size_t)(grow + r) * HH + kc0 + q * 8);
    }
    cp_commit();
}

__device__ void dw_tile(uint32_t sb, int m0, int n0,
                        const float* __restrict__ bd, float* __restrict__ out,
                        int tid, int wid, int lane)
{
    const int wm = wid & 1;
    const int wn = wid >> 1;
    const int lrow = lane & 15;
    const int lsel = (lane >> 4) << 4;

    float acc[4][4][4];
#pragma unroll
    for (int mt = 0; mt < 4; mt++)
#pragma unroll
        for (int nt = 0; nt < 4; nt++)
#pragma unroll
            for (int e = 0; e < 4; e++) acc[mt][nt][e] = 0.f;

    dw_load(sb, m0, n0, 0, tid);
    dw_load(sb, m0, n0, 1, tid);

    for (int c = 0; c < 16; c++) {
        if (c < 15) cp_wait<1>(); else cp_wait<0>();
        __syncthreads();
        if (c + 2 < 16) dw_load(sb, m0, n0, c + 2, tid);

        const uint32_t stg = sb + (uint32_t)(c % 3) * DWSTG;
        const uint32_t a_b = stg + (uint32_t)((wm * 64 + lrow) * 80) + lsel;
        const uint32_t b_b = stg + 10240u + (uint32_t)((wn * 32 + lrow) * 80) + lsel;
#pragma unroll
        for (int s = 0; s < 2; s++) {
            uint32_t bf[2][4];
#pragma unroll
            for (int i = 0; i < 2; i++)
                ldm_x4(bf[i], b_b + (uint32_t)(i * 16 * 80 + s * 32));
#pragma unroll
            for (int mt = 0; mt < 4; mt++) {
                uint32_t a[4];
                ldm_x4(a, a_b + (uint32_t)(mt * 16 * 80 + s * 32));
#pragma unroll
                for (int nt = 0; nt < 4; nt++) {
                    uint32_t b0 = bf[nt >> 1][nt & 1];
                    uint32_t b1 = bf[nt >> 1][(nt & 1) + 2];
                    mma_f16(acc[mt][nt], a, b0, b1);
                }
            }
        }
    }

    const int g = lane >> 2;
    const int tig = lane & 3;
#pragma unroll
    for (int nt = 0; nt < 4; nt++) {
        int col = n0 + wn * 32 + nt * 8 + tig * 2;
        float b0 = __ldg(bd + col);
        float b1 = __ldg(bd + col + 1);
#pragma unroll
        for (int mt = 0; mt < 4; mt++) {
            int r0 = m0 + wm * 64 + mt * 16 + g;
            int r1 = r0 + 8;
            size_t o0 = (size_t)((r0 & 15) * 256 + (r0 >> 4));
            size_t o1 = (size_t)((r1 & 15) * 256 + (r1 >> 4));
            float2 v0 = make_float2(acc[mt][nt][0] + b0, acc[mt][nt][1] + b1);
            float2 v1 = make_float2(acc[mt][nt][2] + b0, acc[mt][nt][3] + b1);
            *(float2*)(out + o0 * VV + col) = v0;
            *(float2*)(out + o1 * VV + col) = v1;
        }
    }
    __syncthreads();
}

// ------------------------- worker loop ------------------------------------------
__device__ void worker_loop(char* lsm,
                            const float* __restrict__ emb,
                            const float* __restrict__ W1,
                            const float* __restrict__ b1,
                            const int* __restrict__ tokens,
                            const float* __restrict__ Wd,
                            const float* __restrict__ bd,
                            float* __restrict__ out,
                            int tid, int wid, int lane)
{
    __shared__ int s_idx;
    for (;;) {
        if (tid == 0) s_idx = (int)atomicAdd(&g_wq, 1u);
        __syncthreads();
        int idx = s_idx;
        if (idx < QN_SGEMM0) {
            job_sgemm0(lsm, idx >> 4, idx & 15, emb, W1, b1, tokens, tid);
        } else if (idx < Q_TB_END) {
            job_transB(lsm, idx - QN_SGEMM0, Wd, tid);
        } else if (idx < Q_DN_END) {
            int d = idx - Q_TB_END;
            int mi = d / NTILE_N, nj = d - mi * NTILE_N;
            if (tid == 0) {
                while (*(volatile unsigned*)&g_tbdone < (unsigned)QN_TRANSB) { }
                while (*(volatile int*)&g_prog < 8 * mi + 8) { }
                __threadfence();
            }
            __syncthreads();
            dw_tile(smem_u32(lsm), mi * 128, nj * 256, bd, out, tid, wid, lane);
        } else {
            break;
        }
    }
}

// ------------------------- fused persistent kernel ------------------------------
#define LSTM_SMEM 157696
__global__ __launch_bounds__(512, 1)
void fused_kernel(const float* __restrict__ emb,
                  const float* __restrict__ W1,
                  const float* __restrict__ b1,
                  const int* __restrict__ tokens,
                  const float* __restrict__ Wd,
                  const float* __restrict__ b2,
                  const float* __restrict__ bd,
                  float* __restrict__ out)
{
    extern __shared__ char lsm[];

    const int tid = threadIdx.x;
    const int wid = tid >> 5;
    const int lane = tid & 31;
    const int bid = blockIdx.x;

    if (bid >= NC_LSTM) {
        worker_loop(lsm, emb, W1, b1, tokens, Wd, bd, out, tid, wid, lane);
        return;
    }

    // ================= LSTM role (R15/R16-proven body, xwrow-gated) =============
    char* Bsl = lsm;
    char* h1st = lsm + 99840;
    char* h2st = lsm + 116480;
    float* zp = (float*)(lsm + 133120);

    const int ct = bid;
    const int hu0 = ct * 8;
    const uint32_t Bsl_a = smem_u32(Bsl);
    const uint32_t h1_a = smem_u32(h1st);
    const uint32_t h2_a = smem_u32(h2st);

    for (int i = tid; i < 6144; i += 512) {
        int mat = i >> 11;
        int rem = i & 2047;
        int n = rem >> 6;
        int ch = rem & 63;
        int gc = (n >> 3) * HH + hu0 + (n & 7);
        cp_async16(Bsl_a + (uint32_t)(mat * 33280 + n * 1040 + ch * 16),
                   g_ut + (size_t)mat * G4H * HH + (size_t)gc * HH + ch * 8);
    }
    cp_commit();
    for (int i = tid; i < 2080; i += 512)
        *(uint4*)(h1st + i * 16) = make_uint4(0, 0, 0, 0);
    cp_wait<0>();
    __syncthreads();

    const int rb = wid;
    const int rn = lane;
    const int rgc = (rn >> 3) * HH + hu0 + (rn & 7);
    const float b2v = __ldg(b2 + rgc);
    const int u7 = rn & 7;

    float creg = 0.f;

    const uint32_t lrow = (uint32_t)(lane & 15) * 1040u;
    const uint32_t lsel = (uint32_t)((lane >> 4) << 4);

    for (int s = 0; s <= TT; s++) {
        if (s < TT && (s & 7) == 0) {
            if (tid == 0) {
                while (*(volatile unsigned*)&g_xwrow[s >> 3] < 16u) { }
                __threadfence();
            }
            __syncthreads();
        }
        float xwv = (s < TT) ? __ldg(&g_xw[((size_t)s * BB + rb) * G4H + rgc]) : 0.f;

        if (s >= 1) {
            const __half* hp = g_h1rh[(s - 1) & 1];
#pragma unroll
            for (int i = 0; i < 2; i++) {
                int u = tid + i * 512;
                int b = u >> 6, ch = u & 63;
                cp_async16(h1_a + (uint32_t)(b * 1040 + ch * 16), hp + b * HH + ch * 8);
            }
            if (s >= 2) {
                const __half* hq = g_h2rh[s & 1];
#pragma unroll
                for (int i = 0; i < 2; i++) {
                    int u = tid + i * 512;
                    int b = u >> 6, ch = u & 63;
                    cp_async16(h2_a + (uint32_t)(b * 1040 + ch * 16), hq + b * HH + ch * 8);
                }
            }
            cp_commit();
            cp_wait<0>();
        }
        __syncthreads();

#pragma unroll
        for (int jj = 0; jj < 2; jj++) {
            int j = (jj == 0) ? wid : (16 + wid);
            if (j < 24) {
                int mat = j >> 3;
                int rem = j & 7;
                int ntile = rem >> 2;
                int ksl = rem & 3;
                uint32_t Ab = ((mat == 2) ? h2_a : h1_a) + (uint32_t)(ksl * 256) + lrow + lsel;
                uint32_t Bb = Bsl_a + (uint32_t)(mat * 33280 + ntile * 16 * 1040 + ksl * 256)
                              + lrow + lsel;
                float acc[2][4] = {{0.f, 0.f, 0.f, 0.f}, {0.f, 0.f, 0.f, 0.f}};
#pragma unroll
                for (int c = 0; c < 8; c++) {
                    uint32_t a[4], bf[4];
                    ldm_x4(a, Ab + (uint32_t)(c * 32));
                    ldm_x4(bf, Bb + (uint32_t)(c * 32));
                    mma_f16(acc[0], a, bf[0], bf[2]);
                    mma_f16(acc[1], a, bf[1], bf[3]);
                }
                int r0 = lane >> 2, c0 = (lane & 3) * 2;
                float* zj = zp + j * 256;
#pragma unroll
                for (int nt = 0; nt < 2; nt++) {
                    zj[r0 * 16 + nt * 8 + c0]           = acc[nt][0];
                    zj[r0 * 16 + nt * 8 + c0 + 1]       = acc[nt][1];
                    zj[(r0 + 8) * 16 + nt * 8 + c0]     = acc[nt][2];
                    zj[(r0 + 8) * 16 + nt * 8 + c0 + 1] = acc[nt][3];
                }
            }
        }
        __syncthreads();

        {
            int ntile = rn >> 4;
            int o16 = rb * 16 + (rn & 15);
            float z1 = xwv, z2 = b2v;
#pragma unroll
            for (int ksl = 0; ksl < 4; ksl++) {
                z1 += zp[(ntile * 4 + ksl) * 256 + o16];
                z2 += zp[(8 + ntile * 4 + ksl) * 256 + o16]
                    + zp[(16 + ntile * 4 + ksl) * 256 + o16];
            }
            float a0 = __shfl_sync(0xffffffffu, z1, u7);
            float a1 = __shfl_sync(0xffffffffu, z1, 8 + u7);
            float a2 = __shfl_sync(0xffffffffu, z1, 16 + u7);
            float a3 = __shfl_sync(0xffffffffu, z1, 24 + u7);
            float d0 = __shfl_sync(0xffffffffu, z2, u7);
            float d1 = __shfl_sync(0xffffffffu, z2, 8 + u7);
            float d2 = __shfl_sync(0xffffffffu, z2, 16 + u7);
            float d3 = __shfl_sync(0xffffffffu, z2, 24 + u7);

            if (rn < 8) {
                if (s < TT) {
                    float ig = fsigmoid(a0);
                    float fg = fsigmoid(a1);
                    float gg = ftanh(a2);
                    float og = fsigmoid(a3);
                    creg = fg * creg + ig * gg;
                    g_h1rh[s & 1][rb * HH + hu0 + u7] = __float2half(og * ftanh(creg));
                }
            } else if (rn < 16) {
                if (s >= 1) {
                    int t = s - 1;
                    float ig = fsigmoid(d0);
                    float fg = fsigmoid(d1);
                    float gg = ftanh(d2);
                    float og = fsigmoid(d3);
                    creg = fg * creg + ig * gg;
                    float h = og * ftanh(creg);
                    __half hh = __float2half(h);
                    g_h2rh[t & 1][rb * HH + hu0 + u7] = hh;
                    g_a_h[((size_t)t * BB + rb) * HH + hu0 + u7] = hh;
                }
            }
        }

        grid_barrier_grp((unsigned)(4 * (s + 1)), lane, wid, ct);
        if (ct == 0 && tid == 0)
            *(volatile int*)&g_prog = s;
    }
}

// ------------------------- launch -----------------------------------------------
extern "C" void kernel_launch(void* const* d_in, const int* in_sizes, int n_in,
                              void* d_out, int out_size)
{
    const int*   tokens = (const int*)  d_in[0];
    const float* emb    = (const float*)d_in[1];
    const float* W1     = (const float*)d_in[2];
    const float* U1     = (const float*)d_in[3];
    const float* b1     = (const float*)d_in[4];
    const float* W2     = (const float*)d_in[5];
    const float* U2     = (const float*)d_in[6];
    const float* b2     = (const float*)d_in[7];
    const float* Wd     = (const float*)d_in[8];
    const float* bd     = (const float*)d_in[9];
    float* out = (float*)d_out;

    cudaFuncSetAttribute(fused_kernel, cudaFuncAttributeMaxDynamicSharedMemorySize,
                         LSTM_SMEM);

    // 1) tiny state reset (graph-replay safe)
    init_kernel<<<1, 64>>>();
    // 2) transU prep (lstm's only prerequisite), ~40us
    prep_kernel<<<3072, 256>>>(U1, W2, U2);
    // 3) persistent kernel: LSTM producer (64 CTAs) + workers (84 CTAs):
    //    sgemm0 (m-major, feeds lstm via xwrow gates) -> transB -> gated dense
    fused_kernel<<<NC_ALL, 512, LSTM_SMEM>>>(emb, W1, b1, tokens, Wd, b2, bd, out);
}